// round 11
// baseline (speedup 1.0000x reference)
#include <cuda_runtime.h>

typedef unsigned long long ull;

#define NB 512
#define NS 1024
#define NL 64
#define NC 66
#define LN2 0.6931471805599453f

static __device__ __forceinline__ ull fma2_(ull a, ull b, ull c) {
    ull d; asm("fma.rn.f32x2 %0, %1, %2, %3;" : "=l"(d) : "l"(a), "l"(b), "l"(c)); return d;
}
static __device__ __forceinline__ ull add2_(ull a, ull b) {
    ull d; asm("add.rn.f32x2 %0, %1, %2;" : "=l"(d) : "l"(a), "l"(b)); return d;
}
static __device__ __forceinline__ ull pack2_(float lo, float hi) {
    ull d; asm("mov.b64 %0, {%1, %2};" : "=l"(d) : "f"(lo), "f"(hi)); return d;
}
static __device__ __forceinline__ float2 unpack2_(ull v) {
    float lo, hi; asm("mov.b64 {%0, %1}, %2;" : "=f"(lo), "=f"(hi) : "l"(v)); return make_float2(lo, hi);
}

__global__ void zero_out_kernel(float* out) { out[0] = 0.0f; }

__global__ void __launch_bounds__(128, 1)
crf_fwd_kernel(const float* __restrict__ pred,
               const int*   __restrict__ ref,
               const int*   __restrict__ seq_len,
               const float* __restrict__ trans,
               float*       __restrict__ out)
{
    __shared__ __align__(16) float qbuf[4][2][64];

    const int w = threadIdx.x >> 5;        // warp = chain (4 per CTA -> 4 SMSPs)
    const int l = threadIdx.x & 31;
    const int b = (blockIdx.x << 2) + w;
    const int j0 = 2 * l, j1 = 2 * l + 1;
    const int L = seq_len[b];

    // E columns for states j0, j1: 128 regs
    ull e0[32], e1[32];
#pragma unroll
    for (int k = 0; k < 32; ++k) {
        e0[k] = pack2_(__expf(trans[(2 * k) * NC + j0]), __expf(trans[(2 * k + 1) * NC + j0]));
        e1[k] = pack2_(__expf(trans[(2 * k) * NC + j1]), __expf(trans[(2 * k + 1) * NC + j1]));
    }
    const float Te0 = __expf(trans[j0 * NC + 65]);
    const float Te1 = __expf(trans[j1 * NC + 65]);

    const float* pb = pred + (size_t)b * NS * NL;
    const float2* p2 = (const float2*)pb;
    const int last = L - 1;

    // init: q1 = exp(pred[0] + T[start]); cur regs carry the live q pair
    float cur0 = __expf(pb[j0] + trans[64 * NC + j0]);
    float cur1 = __expf(pb[j1] + trans[64 * NC + j1]);
    int esum = 0;

    float* buf0 = qbuf[w][0];
    float* buf1 = qbuf[w][1];
    ((float2*)buf0)[l] = make_float2(cur0, cur1);   // q_1 in buf0

    // pred pipeline (depth 3): at top of step t, w0/w1 = exp(row[t-1]-4)
    float2 r1 = p2[(size_t)min(1, last) * 32 + l];
    float2 r2 = p2[(size_t)min(2, last) * 32 + l];
    float w0 = __expf(r1.x - 4.0f);
    float w1 = __expf(r1.y - 4.0f);
    r1 = r2;
    r2 = p2[(size_t)min(3, last) * 32 + l];

    __syncwarp(0xFFFFFFFFu);

    for (int t = 2; t <= L; ++t) {
        const float* rp = (t & 1) ? buf1 : buf0;
        float*       wp = (t & 1) ? buf0 : buf1;
        const ulonglong2* rp2 = (const ulonglong2*)rp;

        // dual matvec: 16 LDS.128 + 64 FFMA2, 8 accumulators
        ull a0 = 0, a1 = 0, a2 = 0, a3 = 0;
        ull c0 = 0, c1 = 0, c2 = 0, c3 = 0;
#pragma unroll
        for (int k = 0; k < 8; ++k) {
            ulonglong2 v0 = rp2[2 * k];
            ulonglong2 v1 = rp2[2 * k + 1];
            a0 = fma2_(v0.x, e0[4 * k + 0], a0);
            c0 = fma2_(v0.x, e1[4 * k + 0], c0);
            a1 = fma2_(v0.y, e0[4 * k + 1], a1);
            c1 = fma2_(v0.y, e1[4 * k + 1], c1);
            a2 = fma2_(v1.x, e0[4 * k + 2], a2);
            c2 = fma2_(v1.x, e1[4 * k + 2], c2);
            a3 = fma2_(v1.y, e0[4 * k + 3], a3);
            c3 = fma2_(v1.y, e1[4 * k + 3], c3);
        }
        float2 fa = unpack2_(add2_(add2_(a0, a1), add2_(a2, a3)));
        float2 fc = unpack2_(add2_(add2_(c0, c1), add2_(c2, c3)));
        float d0 = (fa.x + fa.y) * w0;
        float d1 = (fc.x + fc.y) * w1;

        // renorm every 16 steps (exact power of 2, warp-uniform branch)
        if ((t & 15) == 0) {
            float m = rp[0];
            int e = ((__float_as_int(m) >> 23) & 0xFF) - 127;
            e = max(-100, min(100, e));
            float f = __int_as_float((unsigned)(127 - e) << 23);
            d0 *= f; d1 *= f;
            esum += e;
        }

        cur0 = d0; cur1 = d1;
        ((float2*)wp)[l] = make_float2(d0, d1);

        // pipeline rotate (off the recurrence)
        w0 = __expf(r1.x - 4.0f);
        w1 = __expf(r1.y - 4.0f);
        r1 = r2;
        r2 = p2[(size_t)min(t + 2, last) * 32 + l];

        // warp-synchronous: no divergent branches in this loop, so the warp
        // stays convergent; compiler barrier keeps STS->LDS ordering intact.
        asm volatile("" ::: "memory");
    }

    // terminal capture after the loop (cur = q_L; covers L==1 via init)
    float v = cur0 * Te0 + cur1 * Te1;

    // ---- real path score (lane-strided gather) ----
    float rsum = 0.0f;
    const int* rb = ref + (size_t)b * NS;
    for (int s = l; s < L; s += 32) {
        int r = rb[s];
        int p = (s == 0) ? 64 : rb[s - 1];
        rsum += pb[(size_t)s * NL + r] + trans[p * NC + r];
    }
    if (l == 0) rsum += trans[rb[L - 1] * NC + 65];

    // ---- in-warp reduction; one atomic per chain ----
#pragma unroll
    for (int o = 16; o; o >>= 1) {
        v    += __shfl_xor_sync(0xFFFFFFFFu, v, o);
        rsum += __shfl_xor_sync(0xFFFFFFFFu, rsum, o);
    }
    if (l == 0) {
        float contrib = 4.0f * (float)(L - 1) + LN2 * (float)esum + __logf(v) - rsum;
        atomicAdd(out, contrib);
    }
}

extern "C" void kernel_launch(void* const* d_in, const int* in_sizes, int n_in,
                              void* d_out, int out_size)
{
    const float* pred  = (const float*)d_in[0];
    const int*   refp  = (const int*)d_in[1];
    const int*   seq   = (const int*)d_in[2];
    const float* trans = (const float*)d_in[3];
    float* outp = (float*)d_out;

    zero_out_kernel<<<1, 1>>>(outp);
    crf_fwd_kernel<<<NB / 4, 128>>>(pred, refp, seq, trans, outp);
}

// round 12
// speedup vs baseline: 1.4630x; 1.4630x over previous
#include <cuda_runtime.h>

typedef unsigned long long ull;

#define NB 512
#define NS 1024
#define NL 64
#define NC 66
#define LN2 0.6931471805599453f

static __device__ __forceinline__ ull fma2_(ull a, ull b, ull c) {
    ull d; asm("fma.rn.f32x2 %0, %1, %2, %3;" : "=l"(d) : "l"(a), "l"(b), "l"(c)); return d;
}
static __device__ __forceinline__ ull add2_(ull a, ull b) {
    ull d; asm("add.rn.f32x2 %0, %1, %2;" : "=l"(d) : "l"(a), "l"(b)); return d;
}
static __device__ __forceinline__ ull pack2_(float lo, float hi) {
    ull d; asm("mov.b64 %0, {%1, %2};" : "=l"(d) : "f"(lo), "f"(hi)); return d;
}
static __device__ __forceinline__ float2 unpack2_(ull v) {
    float lo, hi; asm("mov.b64 {%0, %1}, %2;" : "=f"(lo), "=f"(hi) : "l"(v)); return make_float2(lo, hi);
}

__device__ float        g_partial[NB];
__device__ unsigned int g_done = 0;

__global__ void __launch_bounds__(128, 1)
crf_fwd_kernel(const float* __restrict__ pred,
               const int*   __restrict__ ref,
               const int*   __restrict__ seq_len,
               const float* __restrict__ trans,
               float*       __restrict__ out)
{
    __shared__ __align__(16) float qbuf[4][2][64];
    __shared__ int is_last;

    const int w = threadIdx.x >> 5;        // warp = chain
    const int l = threadIdx.x & 31;
    const int b = (blockIdx.x << 2) + w;
    const int j0 = 2 * l, j1 = 2 * l + 1;
    const int L = seq_len[b];

    // E columns for states j0, j1: 128 regs
    ull e0[32], e1[32];
#pragma unroll
    for (int k = 0; k < 32; ++k) {
        e0[k] = pack2_(__expf(trans[(2 * k) * NC + j0]), __expf(trans[(2 * k + 1) * NC + j0]));
        e1[k] = pack2_(__expf(trans[(2 * k) * NC + j1]), __expf(trans[(2 * k + 1) * NC + j1]));
    }
    const float Te0 = __expf(trans[j0 * NC + 65]);
    const float Te1 = __expf(trans[j1 * NC + 65]);

    const float* pb = pred + (size_t)b * NS * NL;
    const float2* p2 = (const float2*)pb;
    const int last = L - 1;

    // init: q1 = exp(pred[0] + T[start]); cur regs carry the live q pair
    float cur0 = __expf(pb[j0] + trans[64 * NC + j0]);
    float cur1 = __expf(pb[j1] + trans[64 * NC + j1]);
    int esum = 0;

    float* buf0 = qbuf[w][0];
    float* buf1 = qbuf[w][1];
    ((float2*)buf0)[l] = make_float2(cur0, cur1);   // q_1 in buf0

    // pred pipeline (depth 3): at top of step t, w0/w1 = exp(row[t-1]-4)
    float2 r1 = p2[(size_t)min(1, last) * 32 + l];
    float2 r2 = p2[(size_t)min(2, last) * 32 + l];
    float w0 = __expf(r1.x - 4.0f);
    float w1 = __expf(r1.y - 4.0f);
    r1 = r2;
    r2 = p2[(size_t)min(3, last) * 32 + l];

    __syncwarp(0xFFFFFFFFu);

// one chain step, compile-time buffers RP -> WP
#define STEP(RP, WP, T)                                                        \
    {                                                                          \
        const ulonglong2* rp2 = (const ulonglong2*)(RP);                       \
        ull a0 = 0, a1 = 0, a2 = 0, a3 = 0;                                    \
        ull c0 = 0, c1 = 0, c2 = 0, c3 = 0;                                    \
        _Pragma("unroll")                                                      \
        for (int k = 0; k < 8; ++k) {                                          \
            ulonglong2 v0 = rp2[2 * k];                                        \
            ulonglong2 v1 = rp2[2 * k + 1];                                    \
            a0 = fma2_(v0.x, e0[4 * k + 0], a0);                               \
            c0 = fma2_(v0.x, e1[4 * k + 0], c0);                               \
            a1 = fma2_(v0.y, e0[4 * k + 1], a1);                               \
            c1 = fma2_(v0.y, e1[4 * k + 1], c1);                               \
            a2 = fma2_(v1.x, e0[4 * k + 2], a2);                               \
            c2 = fma2_(v1.x, e1[4 * k + 2], c2);                               \
            a3 = fma2_(v1.y, e0[4 * k + 3], a3);                               \
            c3 = fma2_(v1.y, e1[4 * k + 3], c3);                               \
        }                                                                      \
        float2 fa = unpack2_(add2_(add2_(a0, a1), add2_(a2, a3)));             \
        float2 fc = unpack2_(add2_(add2_(c0, c1), add2_(c2, c3)));             \
        float d0 = (fa.x + fa.y) * w0;                                         \
        float d1 = (fc.x + fc.y) * w1;                                         \
        if (((T) & 15) == 0) {        /* renorm: exact power of 2 */           \
            float m = (RP)[0];                                                 \
            int e = ((__float_as_int(m) >> 23) & 0xFF) - 127;                  \
            e = max(-100, min(100, e));                                        \
            float f = __int_as_float((unsigned)(127 - e) << 23);               \
            d0 *= f; d1 *= f;                                                  \
            esum += e;                                                         \
        }                                                                      \
        cur0 = d0; cur1 = d1;                                                  \
        ((float2*)(WP))[l] = make_float2(d0, d1);                              \
        w0 = __expf(r1.x - 4.0f);                                              \
        w1 = __expf(r1.y - 4.0f);                                              \
        r1 = r2;                                                               \
        r2 = p2[(size_t)min((T) + 2, last) * 32 + l];                          \
        asm volatile("prefetch.global.L2 [%0];"                                \
                     :: "l"(p2 + (size_t)min((T) + 6, last) * 32 + l));        \
        __syncwarp(0xFFFFFFFFu);                                               \
    }

    int t = 2;
    for (; t + 1 <= L; t += 2) {
        STEP(buf0, buf1, t);
        STEP(buf1, buf0, t + 1);
    }
    if (t <= L) {
        STEP(buf0, buf1, t);
    }
#undef STEP

    // terminal capture after the loop (cur = q_L; covers L==1 via init)
    float v = cur0 * Te0 + cur1 * Te1;

    // ---- real path score (lane-strided gather) ----
    float rsum = 0.0f;
    const int* rb = ref + (size_t)b * NS;
    for (int s = l; s < L; s += 32) {
        int r = rb[s];
        int p = (s == 0) ? 64 : rb[s - 1];
        rsum += pb[(size_t)s * NL + r] + trans[p * NC + r];
    }
    if (l == 0) rsum += trans[rb[L - 1] * NC + 65];

    // ---- in-warp reduction; per-chain partial ----
#pragma unroll
    for (int o = 16; o; o >>= 1) {
        v    += __shfl_xor_sync(0xFFFFFFFFu, v, o);
        rsum += __shfl_xor_sync(0xFFFFFFFFu, rsum, o);
    }
    if (l == 0)
        g_partial[b] = 4.0f * (float)(L - 1) + LN2 * (float)esum + __logf(v) - rsum;

    // ---- last CTA reduces all 512 partials (no separate zero kernel) ----
    __syncthreads();
    if (threadIdx.x == 0) {
        __threadfence();
        unsigned int prev = atomicAdd(&g_done, 1u);
        is_last = (prev == (unsigned)(gridDim.x - 1)) ? 1 : 0;
    }
    __syncthreads();
    if (is_last && w == 0) {
        __threadfence();
        float s = 0.0f;
#pragma unroll
        for (int i = 0; i < NB / 32; ++i)
            s += __ldcg(&g_partial[l + 32 * i]);
#pragma unroll
        for (int o = 16; o; o >>= 1)
            s += __shfl_xor_sync(0xFFFFFFFFu, s, o);
        if (l == 0) {
            out[0] = s;
            atomicExch(&g_done, 0u);   // reset for next graph replay
        }
    }
}

extern "C" void kernel_launch(void* const* d_in, const int* in_sizes, int n_in,
                              void* d_out, int out_size)
{
    const float* pred  = (const float*)d_in[0];
    const int*   refp  = (const int*)d_in[1];
    const int*   seq   = (const int*)d_in[2];
    const float* trans = (const float*)d_in[3];
    float* outp = (float*)d_out;

    crf_fwd_kernel<<<NB / 4, 128>>>(pred, refp, seq, trans, outp);
}